// round 16
// baseline (speedup 1.0000x reference)
#include <cuda_runtime.h>
#include <cuda_bf16.h>
#include <cstdint>

// RaySampler: N=32 cameras, resolution=512 (M=262144 rays/cam).
// Output (fp32): [ray_origins (N,M,3)][ray_dirs (N,M,3)] = 201.3 MB writes.
//
// R14 had the fastest kernel body (28.3us: 1 float4 slot per thread, flat g,
// one div-by-3, 24 regs) but paid 6.6us in graph nodes. R15 fused but bloated
// the body (2-slot loop, 30.5us). This round: fused single kernel with R14's
// exact body shape. Camera is block-uniform (196608 slots/cam % 256 == 0),
// so thread 0 derives the affine params {P,Q,R} AND the 3 prebuilt origin
// float4 patterns into smem; the per-thread path is 4 broadcast LDS.128,
// ~15 FMA, 2 rsqrt, dir selects, 2 coalesced streaming STG.128.

static constexpr int RES = 512;
static constexpr int M_RAYS = RES * RES;                    // 262144
static constexpr int SLOTS_PER_CAM = M_RAYS * 3 / 4;        // 196608 float4s
static constexpr float INV_RES = 1.0f / (float)RES;

__global__ void __launch_bounds__(256)
ray_sampler_kernel(const float* __restrict__ cam,     // (N,4,4)
                   const float* __restrict__ intr,    // (N,3,3)
                   float4* __restrict__ out_org,
                   float4* __restrict__ out_dir)
{
    __shared__ float4 sT[3];    // [0]=P [1]=Q [2]=R (w unused)
    __shared__ float4 sOV[3];   // origin float4 pattern for p=0,1,2

    const unsigned g = blockIdx.x * 256u + threadIdx.x;    // global float4 slot
    const unsigned q = g / 3u;                             // global ray quad
    const int p = (int)(g - q * 3u);                       // window phase

    if (threadIdx.x == 0) {
        const int n = (int)(q >> 16);                      // camera (block-uniform)
        const float* Mn = cam + n * 16;
        const float3 A = make_float3(Mn[0], Mn[4], Mn[8]);     // rot col 0
        const float3 B = make_float3(Mn[1], Mn[5], Mn[9]);     // rot col 1
        const float3 C = make_float3(-Mn[2], -Mn[6], -Mn[10]); // -rot col 2
        const float ox = Mn[3], oy = Mn[7], oz = Mn[11];

        const float* In = intr + n * 9;
        const float fx = In[0], sk = In[1], cx = In[2];
        const float fy = In[4], cy = In[5];
        const float ifx = 1.0f / fx;
        const float ify = 1.0f / fy;

        // Unnormalized dir is affine in pixel: w = P*col + Q*row + R.
        const float s  = sk * ify * ifx;
        const float rx = (cy * sk * ify - cx) * ifx;
        const float ry = cy * ify;

        float3 P, Q, R;
        P.x = A.x * ifx;                 P.y = A.y * ifx;                 P.z = A.z * ifx;
        Q.x = -(A.x * s + B.x * ify);    Q.y = -(A.y * s + B.y * ify);    Q.z = -(A.z * s + B.z * ify);
        R.x = A.x * rx + B.x * ry + C.x; R.y = A.y * rx + B.y * ry + C.y; R.z = A.z * rx + B.z * ry + C.z;

        // Fold pixel scaling x_cam=(col+0.5)/RES, y_cam=(row+0.5)/RES.
        float3 Pp = make_float3(P.x * INV_RES, P.y * INV_RES, P.z * INV_RES);
        float3 Qp = make_float3(Q.x * INV_RES, Q.y * INV_RES, Q.z * INV_RES);
        float3 Rp = make_float3(R.x + 0.5f * (Pp.x + Qp.x),
                                R.y + 0.5f * (Pp.y + Qp.y),
                                R.z + 0.5f * (Pp.z + Qp.z));

        sT[0] = make_float4(Pp.x, Pp.y, Pp.z, 0.f);
        sT[1] = make_float4(Qp.x, Qp.y, Qp.z, 0.f);
        sT[2] = make_float4(Rp.x, Rp.y, Rp.z, 0.f);
        sOV[0] = make_float4(ox, oy, oz, ox);
        sOV[1] = make_float4(oy, oz, ox, oy);
        sOV[2] = make_float4(oz, ox, oy, oz);
    }
    __syncthreads();

    const float4 Pv = sT[0];
    const float4 Qv = sT[1];
    const float4 Rv = sT[2];
    const float4 ov = sOV[p];                 // broadcast LDS, replaces selects

    const float rowf = (float)((q >> 7) & 511u);
    const float colf = (float)(((q & 127u) << 2) + (unsigned)p);   // ray A col

    // base = Q*row + R (shared by rays A and B)
    const float bx = fmaf(Qv.x, rowf, Rv.x);
    const float by = fmaf(Qv.y, rowf, Rv.y);
    const float bz = fmaf(Qv.z, rowf, Rv.z);

    // ray A (col), ray B (col+1) = A + P
    float ax = fmaf(Pv.x, colf, bx);
    float ay = fmaf(Pv.y, colf, by);
    float az = fmaf(Pv.z, colf, bz);
    float ex = ax + Pv.x;
    float ey = ay + Pv.y;
    float ez = az + Pv.z;

    const float ia = rsqrtf(fmaxf(fmaf(ax, ax, fmaf(ay, ay, az * az)), 1e-24f));
    const float ib = rsqrtf(fmaxf(fmaf(ex, ex, fmaf(ey, ey, ez * ez)), 1e-24f));
    ax *= ia; ay *= ia; az *= ia;
    ex *= ib; ey *= ib; ez *= ib;

    float4 dv;
    if (p == 0)      dv = make_float4(ax, ay, az, ex);
    else if (p == 1) dv = make_float4(ay, az, ex, ey);
    else             dv = make_float4(az, ex, ey, ez);

    __stcs(&out_dir[g], dv);    // coalesced streaming stores
    __stcs(&out_org[g], ov);
}

extern "C" void kernel_launch(void* const* d_in, const int* in_sizes, int n_in,
                              void* d_out, int out_size)
{
    const float* cam  = (const float*)d_in[0];   // (N,4,4) fp32
    const float* intr = (const float*)d_in[1];   // (N,3,3) fp32
    const int N = in_sizes[0] / 16;              // 32

    const size_t T4 = (size_t)N * SLOTS_PER_CAM; // 6,291,456 float4s
    float4* out_org = (float4*)d_out;
    float4* out_dir = (float4*)d_out + T4;

    dim3 block(256);
    dim3 grid((unsigned)(T4 / 256));             // 24576 blocks, exact
    ray_sampler_kernel<<<grid, block>>>(cam, intr, out_org, out_dir);
}